// round 3
// baseline (speedup 1.0000x reference)
#include <cuda_runtime.h>

#define NC 24
#define LH 256
#define LW 256
#define PLANE (LH*LW)
#define R 8
#define EPSF 1e-4f
#define RING 18
#define STRIP 32

// A,B coefficient planes (allocation-free rule: __device__ globals)
__device__ float g_A[NC*PLANE];
__device__ float g_B[NC*PLANE];

// ---------------------------------------------------------------------------
// Fused LR kernel: horizontal window sums via block shuffle-scan, vertical
// truncated sliding window via smem ring buffer, then solve A,B.
// Grid: (8 y-strips of 32, NC planes), 256 threads = columns.
//
// Shared layout (dynamic):
//   ring[4][RING][256]  : horizontal window sums for rows in flight
//   C[4][256]           : cumsum scratch for current row
//   ws[32]              : per-warp totals (8 warps x 4 arrays)
// ---------------------------------------------------------------------------
__global__ void k_lr_stats(const float* __restrict__ p, const float* __restrict__ I)
{
    extern __shared__ float sm[];
    float* ringI  = sm;                  // RING*256
    float* ringP  = ringI  + RING*LW;
    float* ringIP = ringP  + RING*LW;
    float* ringII = ringIP + RING*LW;
    float* C      = ringII + RING*LW;    // 4*256
    float* ws     = C + 4*LW;            // 32

    const int pl   = blockIdx.y;
    const int y0   = blockIdx.x * STRIP;
    const int x    = threadIdx.x;
    const int lane = x & 31;
    const int warp = x >> 5;

    const float* __restrict__ Ip = I + pl*PLANE;
    const float* __restrict__ Pp = p + pl*PLANE;

    const int hiX = min(x + R, LW - 1);
    const int loX = x - R - 1;          // index into cumsum (may be <0)

    float sI = 0.f, sP = 0.f, sIP = 0.f, sII = 0.f;

    // ---- helper expanded inline via macro: compute hsum of row `ry`, store in
    //      ring slot ry%RING, and accumulate sign ( +1 for add ) into sums ----
#define HSUM_ROW_ADD(ry)                                                        \
    {                                                                           \
        const int rb = (ry)*LW;                                                 \
        float vi = Ip[rb + x];                                                  \
        float vp = Pp[rb + x];                                                  \
        float a = vi, b = vp, c = vi*vp, d = vi*vi;                             \
        _Pragma("unroll")                                                       \
        for (int off = 1; off < 32; off <<= 1) {                                \
            float ta = __shfl_up_sync(0xffffffffu, a, off);                     \
            float tb = __shfl_up_sync(0xffffffffu, b, off);                     \
            float tc = __shfl_up_sync(0xffffffffu, c, off);                     \
            float td = __shfl_up_sync(0xffffffffu, d, off);                     \
            if (lane >= off) { a += ta; b += tb; c += tc; d += td; }            \
        }                                                                       \
        if (lane == 31) {                                                       \
            ws[warp] = a; ws[8+warp] = b; ws[16+warp] = c; ws[24+warp] = d;     \
        }                                                                       \
        __syncthreads();                                                        \
        float oa = 0.f, ob = 0.f, oc = 0.f, od = 0.f;                           \
        for (int j = 0; j < warp; j++) {                                        \
            oa += ws[j]; ob += ws[8+j]; oc += ws[16+j]; od += ws[24+j];         \
        }                                                                       \
        a += oa; b += ob; c += oc; d += od;                                     \
        C[x] = a; C[LW+x] = b; C[2*LW+x] = c; C[3*LW+x] = d;                    \
        __syncthreads();                                                        \
        float wa = C[hiX], wb = C[LW+hiX], wc = C[2*LW+hiX], wd = C[3*LW+hiX];  \
        if (loX >= 0) {                                                         \
            wa -= C[loX]; wb -= C[LW+loX]; wc -= C[2*LW+loX]; wd -= C[3*LW+loX];\
        }                                                                       \
        const int slot = ((ry) % RING)*LW + x;                                  \
        ringI[slot] = wa; ringP[slot] = wb; ringIP[slot] = wc; ringII[slot] = wd;\
        sI += wa; sP += wb; sIP += wc; sII += wd;                               \
        __syncthreads();                                                        \
    }

    // init: rows [max(y0-R,0), min(y0+R,255)]
    {
        const int lo = max(y0 - R, 0);
        const int hi = min(y0 + R, LH - 1);
        for (int ry = lo; ry <= hi; ry++) {
            HSUM_ROW_ADD(ry)
        }
    }

    const float fcx = (float)(hiX - max(x - R, 0) + 1);
    float* __restrict__ Ap = g_A + pl*PLANE;
    float* __restrict__ Bp = g_B + pl*PLANE;

    for (int yo = y0; yo < y0 + STRIP; yo++) {
        const int   cy  = min(yo + R, LH - 1) - max(yo - R, 0) + 1;
        const float inv = 1.0f / (fcx * (float)cy);

        const float mI  = sI  * inv;
        const float mP  = sP  * inv;
        const float cov = sIP * inv - mI*mP;
        const float var = sII * inv - mI*mI;
        const float A   = cov / (var + EPSF);
        const float B   = mP - A*mI;

        Ap[yo*LW + x] = A;
        Bp[yo*LW + x] = B;

        // subtract row yo-R (read from ring before its slot can be reused)
        const int ys = yo - R;
        if (ys >= 0) {
            const int slot = (ys % RING)*LW + x;
            sI -= ringI[slot]; sP -= ringP[slot];
            sIP -= ringIP[slot]; sII -= ringII[slot];
        }
        // add row yo+R+1
        const int ya = yo + R + 1;
        if (ya <= LH - 1) {
            HSUM_ROW_ADD(ya)
        }
    }
#undef HSUM_ROW_ADD
}

// ---------------------------------------------------------------------------
// Upsample x4 (half-pixel bilinear, edge clamp == jax linear) + apply.
// One block per (HR row, plane); 256 threads, 4 px each (float4).
// Y-lerped A,B rows staged cooperatively in smem.
// ---------------------------------------------------------------------------
__global__ void k_apply(const float* __restrict__ Ihr, float* __restrict__ out)
{
    __shared__ float aL[LW], bL[LW];

    const int Y  = blockIdx.x;
    const int pl = blockIdx.y;
    const int t  = threadIdx.x;

    const float yf  = 0.25f * (float)Y - 0.375f;
    const int   y0  = (int)floorf(yf);
    const float wy  = yf - (float)y0;
    const int   y0c = max(y0, 0);
    const int   y1c = min(y0 + 1, LH - 1);

    const float* __restrict__ A = g_A + pl*PLANE;
    const float* __restrict__ B = g_B + pl*PLANE;

    {
        const float a0 = A[y0c*LW + t];
        const float a1 = A[y1c*LW + t];
        const float b0 = B[y0c*LW + t];
        const float b1 = B[y1c*LW + t];
        aL[t] = a0 + wy*(a1 - a0);
        bL[t] = b0 + wy*(b1 - b0);
    }
    __syncthreads();

    const int xm = max(t - 1, 0);
    const int xp = min(t + 1, LW - 1);

    const float am = aL[xm], a0 = aL[t], ap = aL[xp];
    const float bm = bL[xm], b0 = bL[t], bp = bL[xp];

    const int idx = ((pl << 10) + Y) * 1024 + (t << 2);
    const float4 iv = __ldcs(reinterpret_cast<const float4*>(Ihr + idx));

    float4 ov;
    ov.x = (0.375f*am + 0.625f*a0)*iv.x + (0.375f*bm + 0.625f*b0);
    ov.y = (0.125f*am + 0.875f*a0)*iv.y + (0.125f*bm + 0.875f*b0);
    ov.z = (0.875f*a0 + 0.125f*ap)*iv.z + (0.875f*b0 + 0.125f*bp);
    ov.w = (0.625f*a0 + 0.375f*ap)*iv.w + (0.625f*b0 + 0.375f*bp);

    __stcs(reinterpret_cast<float4*>(out + idx), ov);
}

// ---------------------------------------------------------------------------
extern "C" void kernel_launch(void* const* d_in, const int* in_sizes, int n_in,
                              void* d_out, int out_size)
{
    const float* p_lr = (const float*)d_in[0];
    const float* I_lr = (const float*)d_in[1];
    const float* I_hr = (const float*)d_in[2];
    float* out = (float*)d_out;

    // ring(4*RING*256) + C(4*256) + ws(32) floats
    const int smem_bytes = (4*RING*LW + 4*LW + 32) * (int)sizeof(float);
    cudaFuncSetAttribute(k_lr_stats,
                         cudaFuncAttributeMaxDynamicSharedMemorySize, smem_bytes);

    k_lr_stats<<<dim3(LH/STRIP, NC), LW, smem_bytes>>>(p_lr, I_lr);
    k_apply   <<<dim3(1024, NC), LW>>>(I_hr, out);
}

// round 5
// speedup vs baseline: 1.3734x; 1.3734x over previous
#include <cuda_runtime.h>

#define NC 24
#define LH 256
#define LW 256
#define PLANE (LH*LW)
#define R 8
#define EPSF 1e-4f
#define SROW 272   // 8 zero-halo + 256 + 8 zero-halo

// scratch (allocation-free rule: __device__ globals)
__device__ float g_hI [NC*PLANE];
__device__ float g_hP [NC*PLANE];
__device__ float g_hIP[NC*PLANE];
__device__ float g_hII[NC*PLANE];
__device__ float g_A  [NC*PLANE];
__device__ float g_B  [NC*PLANE];

// ---------------------------------------------------------------------------
// Kernel 1: horizontal truncated window sums of I, p, I*p, I*I.
// Truncated window == full 17-tap window over a zero-padded row.
// Block = 4 rows x 64 threads; each thread -> 4 columns via running sums.
// Per thread per array: 5 LDS.128 + ~23 adds.
// ---------------------------------------------------------------------------
__global__ void k_hbox(const float* __restrict__ p, const float* __restrict__ I)
{
    __shared__ __align__(16) float s[4][4][SROW];  // [rowInBlk][array][8+col]

    const int tid = threadIdx.x;
    const int r   = tid >> 6;        // row in block, 0..3
    const int tx  = tid & 63;        // 0..63
    const int row = blockIdx.x * 4 + r;
    const int pl  = blockIdx.y;
    const int gbase = pl*PLANE + row*LW;
    const int xb  = tx << 2;         // output column base

    // zero the halos
    if (tx == 0) {
        #pragma unroll
        for (int j = 0; j < 8; j++) {
            s[r][0][j] = 0.f; s[r][1][j] = 0.f; s[r][2][j] = 0.f; s[r][3][j] = 0.f;
        }
    } else if (tx == 1) {
        #pragma unroll
        for (int j = 264; j < 272; j++) {
            s[r][0][j] = 0.f; s[r][1][j] = 0.f; s[r][2][j] = 0.f; s[r][3][j] = 0.f;
        }
    }

    const float4 vi = *reinterpret_cast<const float4*>(I + gbase + xb);
    const float4 vp = *reinterpret_cast<const float4*>(p + gbase + xb);
    *reinterpret_cast<float4*>(&s[r][0][8 + xb]) = vi;
    *reinterpret_cast<float4*>(&s[r][1][8 + xb]) = vp;
    *reinterpret_cast<float4*>(&s[r][2][8 + xb]) =
        make_float4(vi.x*vp.x, vi.y*vp.y, vi.z*vp.z, vi.w*vp.w);
    *reinterpret_cast<float4*>(&s[r][3][8 + xb]) =
        make_float4(vi.x*vi.x, vi.y*vi.y, vi.z*vi.z, vi.w*vi.w);
    __syncthreads();

    // window for output col xb starts at padded index (8 + xb - 8) = xb
#define HPROC(ARR, DST)                                                         \
    {                                                                           \
        const float4 q0 = *reinterpret_cast<const float4*>(&s[r][ARR][xb]);     \
        const float4 q1 = *reinterpret_cast<const float4*>(&s[r][ARR][xb+4]);   \
        const float4 q2 = *reinterpret_cast<const float4*>(&s[r][ARR][xb+8]);   \
        const float4 q3 = *reinterpret_cast<const float4*>(&s[r][ARR][xb+12]);  \
        const float4 q4 = *reinterpret_cast<const float4*>(&s[r][ARR][xb+16]);  \
        float w0 = q0.x+q0.y+q0.z+q0.w + q1.x+q1.y+q1.z+q1.w                    \
                 + q2.x+q2.y+q2.z+q2.w + q3.x+q3.y+q3.z+q3.w + q4.x;            \
        float w1 = w0 - q0.x + q4.y;                                            \
        float w2 = w1 - q0.y + q4.z;                                            \
        float w3 = w2 - q0.z + q4.w;                                            \
        *reinterpret_cast<float4*>(DST + gbase + xb) = make_float4(w0,w1,w2,w3);\
    }
    HPROC(0, g_hI)
    HPROC(1, g_hP)
    HPROC(2, g_hIP)
    HPROC(3, g_hII)
#undef HPROC
}

// ---------------------------------------------------------------------------
// Kernel 2: vertical truncated sliding window + solve A,B.
// 128 threads, each owns 2 columns (float2). Chunk = 16 output rows.
// ---------------------------------------------------------------------------
__global__ void k_vbox()
{
    const int pl = blockIdx.y;
    const int t  = threadIdx.x;       // 0..127
    const int c  = t << 1;            // column base
    const int y0 = blockIdx.x * 16;

    const float* __restrict__ hI  = g_hI  + pl*PLANE + c;
    const float* __restrict__ hP  = g_hP  + pl*PLANE + c;
    const float* __restrict__ hIP = g_hIP + pl*PLANE + c;
    const float* __restrict__ hII = g_hII + pl*PLANE + c;

    float2 sI  = make_float2(0.f,0.f), sP  = make_float2(0.f,0.f);
    float2 sIP = make_float2(0.f,0.f), sII = make_float2(0.f,0.f);

#define ADDROW(YY)                                                        \
    {                                                                     \
        const int o = (YY)*LW;                                            \
        const float2 a = *reinterpret_cast<const float2*>(hI  + o);       \
        const float2 b = *reinterpret_cast<const float2*>(hP  + o);       \
        const float2 d = *reinterpret_cast<const float2*>(hIP + o);       \
        const float2 e = *reinterpret_cast<const float2*>(hII + o);       \
        sI.x += a.x; sI.y += a.y;  sP.x += b.x; sP.y += b.y;              \
        sIP.x += d.x; sIP.y += d.y; sII.x += e.x; sII.y += e.y;           \
    }
#define SUBROW(YY)                                                        \
    {                                                                     \
        const int o = (YY)*LW;                                            \
        const float2 a = *reinterpret_cast<const float2*>(hI  + o);       \
        const float2 b = *reinterpret_cast<const float2*>(hP  + o);       \
        const float2 d = *reinterpret_cast<const float2*>(hIP + o);       \
        const float2 e = *reinterpret_cast<const float2*>(hII + o);       \
        sI.x -= a.x; sI.y -= a.y;  sP.x -= b.x; sP.y -= b.y;              \
        sIP.x -= d.x; sIP.y -= d.y; sII.x -= e.x; sII.y -= e.y;           \
    }

    {
        const int lo = max(y0 - R, 0);
        const int hi = y0 + R;        // y0 <= 240 -> hi <= 248 < 256 always
        for (int yy = lo; yy <= hi; yy++) ADDROW(yy)
    }

    // count_x(c) = min(c+R, LW-1) - max(c-R, 0) + 1
    const float cx0 = (float)(min(c   + R, LW-1) - max(c   - R, 0) + 1);
    const float cx1 = (float)(min(c+1 + R, LW-1) - max(c+1 - R, 0) + 1);

    float* __restrict__ Ap = g_A + pl*PLANE + c;
    float* __restrict__ Bp = g_B + pl*PLANE + c;

    for (int yo = y0; yo < y0 + 16; yo++) {
        const float cy   = (float)(min(yo + R, LH-1) - max(yo - R, 0) + 1);
        const float inv0 = 1.0f / (cx0 * cy);
        const float inv1 = 1.0f / (cx1 * cy);

        const float mI0 = sI.x*inv0,  mI1 = sI.y*inv1;
        const float mP0 = sP.x*inv0,  mP1 = sP.y*inv1;
        const float A0  = (sIP.x*inv0 - mI0*mP0) / ((sII.x*inv0 - mI0*mI0) + EPSF);
        const float A1  = (sIP.y*inv1 - mI1*mP1) / ((sII.y*inv1 - mI1*mI1) + EPSF);
        const float B0  = mP0 - A0*mI0;
        const float B1  = mP1 - A1*mI1;

        const int o = yo*LW;
        *reinterpret_cast<float2*>(Ap + o) = make_float2(A0, A1);
        *reinterpret_cast<float2*>(Bp + o) = make_float2(B0, B1);

        const int ya = yo + R + 1;
        if (ya <= LH - 1) ADDROW(ya)
        const int ysub = yo - R;
        if (ysub >= 0) SUBROW(ysub)
    }
#undef ADDROW
#undef SUBROW
}

// ---------------------------------------------------------------------------
// Kernel 3: x4 bilinear upsample (half-pixel, edge clamp == jax linear) + apply.
// Block = one LR row group k covering HR rows 4k..4k+3 (they only need LR rows
// k-1,k,k+1). 256 threads; each thread -> 4x4 = 16 output px (4 float4 ld/st).
// ---------------------------------------------------------------------------
__global__ void k_apply(const float* __restrict__ Ihr, float* __restrict__ out)
{
    __shared__ float sA[3][LW], sB[3][LW];

    const int k  = blockIdx.x;        // 0..255
    const int pl = blockIdx.y;
    const int t  = threadIdx.x;

    const int km = max(k - 1, 0);
    const int kp = min(k + 1, LH - 1);

    const float* __restrict__ A = g_A + pl*PLANE;
    const float* __restrict__ B = g_B + pl*PLANE;

    sA[0][t] = A[km*LW + t];  sA[1][t] = A[k*LW + t];  sA[2][t] = A[kp*LW + t];
    sB[0][t] = B[km*LW + t];  sB[1][t] = B[k*LW + t];  sB[2][t] = B[kp*LW + t];
    __syncthreads();

    const int xm = max(t - 1, 0);
    const int xp = min(t + 1, LW - 1);

    float xA[3][4], xB[3][4];
    #pragma unroll
    for (int j = 0; j < 3; j++) {
        const float am = sA[j][xm], a0 = sA[j][t], ap = sA[j][xp];
        const float bm = sB[j][xm], b0 = sB[j][t], bp = sB[j][xp];
        xA[j][0] = 0.375f*am + 0.625f*a0;  xB[j][0] = 0.375f*bm + 0.625f*b0;
        xA[j][1] = 0.125f*am + 0.875f*a0;  xB[j][1] = 0.125f*bm + 0.875f*b0;
        xA[j][2] = 0.875f*a0 + 0.125f*ap;  xB[j][2] = 0.875f*b0 + 0.125f*bp;
        xA[j][3] = 0.625f*a0 + 0.375f*ap;  xB[j][3] = 0.625f*b0 + 0.375f*bp;
    }

    const int base = ((pl << 10) + (k << 2)) * 1024 + (t << 2);
    const float4 iv0 = __ldcs(reinterpret_cast<const float4*>(Ihr + base));
    const float4 iv1 = __ldcs(reinterpret_cast<const float4*>(Ihr + base + 1024));
    const float4 iv2 = __ldcs(reinterpret_cast<const float4*>(Ihr + base + 2048));
    const float4 iv3 = __ldcs(reinterpret_cast<const float4*>(Ihr + base + 3072));

    // y-weights: HR row 4k+0: LR rows (k-1,k) w=(.375,.625); 4k+1: (.125,.875)
    //            4k+2: LR rows (k,k+1) w=(.875,.125);        4k+3: (.625,.375)
#define OUTV(IV, W0, J0, W1, J1)                                                \
    make_float4(                                                                \
        (W0*xA[J0][0] + W1*xA[J1][0])*IV.x + (W0*xB[J0][0] + W1*xB[J1][0]),     \
        (W0*xA[J0][1] + W1*xA[J1][1])*IV.y + (W0*xB[J0][1] + W1*xB[J1][1]),     \
        (W0*xA[J0][2] + W1*xA[J1][2])*IV.z + (W0*xB[J0][2] + W1*xB[J1][2]),     \
        (W0*xA[J0][3] + W1*xA[J1][3])*IV.w + (W0*xB[J0][3] + W1*xB[J1][3]))

    __stcs(reinterpret_cast<float4*>(out + base),        OUTV(iv0, 0.375f, 0, 0.625f, 1));
    __stcs(reinterpret_cast<float4*>(out + base + 1024), OUTV(iv1, 0.125f, 0, 0.875f, 1));
    __stcs(reinterpret_cast<float4*>(out + base + 2048), OUTV(iv2, 0.875f, 1, 0.125f, 2));
    __stcs(reinterpret_cast<float4*>(out + base + 3072), OUTV(iv3, 0.625f, 1, 0.375f, 2));
#undef OUTV
}

// ---------------------------------------------------------------------------
extern "C" void kernel_launch(void* const* d_in, const int* in_sizes, int n_in,
                              void* d_out, int out_size)
{
    const float* p_lr = (const float*)d_in[0];
    const float* I_lr = (const float*)d_in[1];
    const float* I_hr = (const float*)d_in[2];
    float* out = (float*)d_out;

    k_hbox <<<dim3(LH/4,  NC), 256>>>(p_lr, I_lr);
    k_vbox <<<dim3(LH/16, NC), 128>>>();
    k_apply<<<dim3(LH,    NC), 256>>>(I_hr, out);
}

// round 6
// speedup vs baseline: 1.4218x; 1.0352x over previous
#include <cuda_runtime.h>

#define NC 24
#define LH 256
#define LW 256
#define PLANE (LH*LW)
#define R 8
#define EPSF 1e-4f

// scratch (allocation-free rule: __device__ globals)
// g_h4[pixel] = {hsumI, hsumP, hsumIP, hsumII}
__device__ float4 g_h4[NC*PLANE];
// g_AB[pixel] = {A, B}
__device__ float2 g_AB[NC*PLANE];

// ---------------------------------------------------------------------------
// Kernel 1: horizontal truncated window sums of I, p, I*p, I*I.
// Truncated window == full 17-tap window over a zero-padded row.
// No smem, no barriers: each thread owns 4 columns of one row; the 5 float4
// window chunks are 16B-aligned and each is fully in- or out-of-range, so
// zero padding is one predicate per load. 10 independent LDG.128 per thread.
// Block = 256 threads = 4 rows x 64 col-groups. Grid = (64, NC).
// ---------------------------------------------------------------------------
__device__ __forceinline__ float4 ldz(const float* __restrict__ row, int col)
{
    if (col < 0 || col >= LW) return make_float4(0.f, 0.f, 0.f, 0.f);
    return *reinterpret_cast<const float4*>(row + col);
}

__global__ void k_hbox(const float* __restrict__ p, const float* __restrict__ I)
{
    const int tid = threadIdx.x;
    const int r   = tid >> 6;          // row in block 0..3
    const int tx  = tid & 63;
    const int row = blockIdx.x * 4 + r;
    const int pl  = blockIdx.y;
    const int gbase = pl*PLANE + row*LW;
    const int xb  = tx << 2;           // first output column

    const float* __restrict__ Irow = I + gbase;
    const float* __restrict__ Prow = p + gbase;

    // window for outputs xb..xb+3 spans columns [xb-8, xb+11]
    float4 i4[5], p4[5];
    #pragma unroll
    for (int j = 0; j < 5; j++) {
        const int col = xb - 8 + 4*j;
        i4[j] = ldz(Irow, col);
        p4[j] = ldz(Prow, col);
    }

    // flatten to 20-element arrays
    float iv[20], pv[20];
    #pragma unroll
    for (int j = 0; j < 5; j++) {
        iv[4*j+0] = i4[j].x; iv[4*j+1] = i4[j].y; iv[4*j+2] = i4[j].z; iv[4*j+3] = i4[j].w;
        pv[4*j+0] = p4[j].x; pv[4*j+1] = p4[j].y; pv[4*j+2] = p4[j].z; pv[4*j+3] = p4[j].w;
    }

    float sI = 0.f, sP = 0.f, sIP = 0.f, sII = 0.f;
    #pragma unroll
    for (int j = 0; j < 17; j++) {
        sI += iv[j]; sP += pv[j]; sIP += iv[j]*pv[j]; sII += iv[j]*iv[j];
    }

    float4* __restrict__ dst = g_h4 + gbase + xb;
    float4 w = make_float4(sI, sP, sIP, sII);
    dst[0] = w;
    #pragma unroll
    for (int k = 1; k < 4; k++) {
        sI  += iv[16+k] - iv[k-1];
        sP  += pv[16+k] - pv[k-1];
        sIP += iv[16+k]*pv[16+k] - iv[k-1]*pv[k-1];
        sII += iv[16+k]*iv[16+k] - iv[k-1]*iv[k-1];
        dst[k] = make_float4(sI, sP, sIP, sII);
    }
}

// ---------------------------------------------------------------------------
// Kernel 2: vertical truncated sliding window + solve A,B.
// 256 threads, 1 column each; one LDG.128 per add/sub row-step.
// Chunk = 16 output rows. Grid = (16, NC).
// ---------------------------------------------------------------------------
__global__ void k_vbox()
{
    const int pl = blockIdx.y;
    const int c  = threadIdx.x;       // column
    const int y0 = blockIdx.x * 16;

    const float4* __restrict__ h = g_h4 + pl*PLANE + c;

    float sI = 0.f, sP = 0.f, sIP = 0.f, sII = 0.f;

    {
        const int lo = max(y0 - R, 0);
        const int hi = y0 + R;        // y0 <= 240 -> hi <= 248 < 256 always
        for (int yy = lo; yy <= hi; yy++) {
            const float4 v = h[yy*LW];
            sI += v.x; sP += v.y; sIP += v.z; sII += v.w;
        }
    }

    const float cx = (float)(min(c + R, LW-1) - max(c - R, 0) + 1);

    float2* __restrict__ ABp = g_AB + pl*PLANE + c;

    for (int yo = y0; yo < y0 + 16; yo++) {
        const float cy  = (float)(min(yo + R, LH-1) - max(yo - R, 0) + 1);
        const float inv = 1.0f / (cx * cy);

        const float mI = sI*inv;
        const float mP = sP*inv;
        const float A  = (sIP*inv - mI*mP) / ((sII*inv - mI*mI) + EPSF);
        const float B  = mP - A*mI;

        ABp[yo*LW] = make_float2(A, B);

        const int ya = yo + R + 1;
        if (ya <= LH - 1) {
            const float4 v = h[ya*LW];
            sI += v.x; sP += v.y; sIP += v.z; sII += v.w;
        }
        const int ysub = yo - R;
        if (ysub >= 0) {
            const float4 v = h[ysub*LW];
            sI -= v.x; sP -= v.y; sIP -= v.z; sII -= v.w;
        }
    }
}

// ---------------------------------------------------------------------------
// Kernel 3: x4 bilinear upsample (half-pixel, edge clamp == jax linear) + apply.
// Block = LR row k -> HR rows 4k..4k+3 (need LR rows k-1,k,k+1 only).
// 256 threads; each thread -> 4x4 = 16 output px (4 independent float4 ld/st).
// ---------------------------------------------------------------------------
__global__ void k_apply(const float* __restrict__ Ihr, float* __restrict__ out)
{
    __shared__ float2 sAB[3][LW];

    const int k  = blockIdx.x;        // 0..255
    const int pl = blockIdx.y;
    const int t  = threadIdx.x;

    const int km = max(k - 1, 0);
    const int kp = min(k + 1, LH - 1);

    const float2* __restrict__ AB = g_AB + pl*PLANE;
    sAB[0][t] = AB[km*LW + t];
    sAB[1][t] = AB[k *LW + t];
    sAB[2][t] = AB[kp*LW + t];
    __syncthreads();

    const int xm = max(t - 1, 0);
    const int xp = min(t + 1, LW - 1);

    float xA[3][4], xB[3][4];
    #pragma unroll
    for (int j = 0; j < 3; j++) {
        const float2 vm = sAB[j][xm], v0 = sAB[j][t], vp = sAB[j][xp];
        xA[j][0] = 0.375f*vm.x + 0.625f*v0.x;  xB[j][0] = 0.375f*vm.y + 0.625f*v0.y;
        xA[j][1] = 0.125f*vm.x + 0.875f*v0.x;  xB[j][1] = 0.125f*vm.y + 0.875f*v0.y;
        xA[j][2] = 0.875f*v0.x + 0.125f*vp.x;  xB[j][2] = 0.875f*v0.y + 0.125f*vp.y;
        xA[j][3] = 0.625f*v0.x + 0.375f*vp.x;  xB[j][3] = 0.625f*v0.y + 0.375f*vp.y;
    }

    const int base = ((pl << 10) + (k << 2)) * 1024 + (t << 2);
    const float4 iv0 = __ldcs(reinterpret_cast<const float4*>(Ihr + base));
    const float4 iv1 = __ldcs(reinterpret_cast<const float4*>(Ihr + base + 1024));
    const float4 iv2 = __ldcs(reinterpret_cast<const float4*>(Ihr + base + 2048));
    const float4 iv3 = __ldcs(reinterpret_cast<const float4*>(Ihr + base + 3072));

    // y-weights: HR row 4k+0: LR rows (k-1,k) w=(.375,.625); 4k+1: (.125,.875)
    //            4k+2: LR rows (k,k+1) w=(.875,.125);        4k+3: (.625,.375)
#define OUTV(IV, W0, J0, W1, J1)                                                \
    make_float4(                                                                \
        (W0*xA[J0][0] + W1*xA[J1][0])*IV.x + (W0*xB[J0][0] + W1*xB[J1][0]),     \
        (W0*xA[J0][1] + W1*xA[J1][1])*IV.y + (W0*xB[J0][1] + W1*xB[J1][1]),     \
        (W0*xA[J0][2] + W1*xA[J1][2])*IV.z + (W0*xB[J0][2] + W1*xB[J1][2]),     \
        (W0*xA[J0][3] + W1*xA[J1][3])*IV.w + (W0*xB[J0][3] + W1*xB[J1][3]))

    __stcs(reinterpret_cast<float4*>(out + base),        OUTV(iv0, 0.375f, 0, 0.625f, 1));
    __stcs(reinterpret_cast<float4*>(out + base + 1024), OUTV(iv1, 0.125f, 0, 0.875f, 1));
    __stcs(reinterpret_cast<float4*>(out + base + 2048), OUTV(iv2, 0.875f, 1, 0.125f, 2));
    __stcs(reinterpret_cast<float4*>(out + base + 3072), OUTV(iv3, 0.625f, 1, 0.375f, 2));
#undef OUTV
}

// ---------------------------------------------------------------------------
extern "C" void kernel_launch(void* const* d_in, const int* in_sizes, int n_in,
                              void* d_out, int out_size)
{
    const float* p_lr = (const float*)d_in[0];
    const float* I_lr = (const float*)d_in[1];
    const float* I_hr = (const float*)d_in[2];
    float* out = (float*)d_out;

    k_hbox <<<dim3(LH/4,  NC), 256>>>(p_lr, I_lr);
    k_vbox <<<dim3(LH/16, NC), 256>>>();
    k_apply<<<dim3(LH,    NC), 256>>>(I_hr, out);
}